// round 2
// baseline (speedup 1.0000x reference)
#include <cuda_runtime.h>
#include <math.h>

typedef unsigned long long ull;

#define N_B 8
#define C_IN 64
#define C_H 32
#define HI 384
#define WI 384
#define HO 192
#define WO 192
#define HWI (HI*WI)
#define HWO (HO*WO)
#define NPIX_CH (N_B*HWO)

// ---------------- scratch ----------------
__device__ float g_mean[N_B*C_IN];
__device__ float g_att[2*N_B*4];
__device__ float g_sqw[C_IN*9*128];          // [ci][k9][co*2 duplicated]
__device__ float g_wv[N_B*C_H*3*64];         // [n][ci][kh][co*2 duplicated]
__device__ float g_wh[N_B*C_H*3*64];
__device__ float g_vraw[(size_t)N_B*C_H*HWO];
__device__ float g_hraw[(size_t)N_B*C_H*HWO];
__device__ float g_stats[2*C_H*2];

// ---------------- f32x2 helpers ----------------
__device__ __forceinline__ void unpack2(ull v, float& a, float& b) {
    asm("mov.b64 {%0, %1}, %2;" : "=f"(a), "=f"(b) : "l"(v));
}
__device__ __forceinline__ void ffma2(ull& d, ull a, ull b) {
    asm("fma.rn.f32x2 %0, %1, %2, %0;" : "+l"(d) : "l"(a), "l"(b));
}

// ---------------- 1) channel means ----------------
__global__ void mean_kernel(const float* __restrict__ x) {
    int nc = blockIdx.x;
    const float4* p = (const float4*)(x + (size_t)nc * HWI);
    float s = 0.f;
    for (int i = threadIdx.x; i < HWI/4; i += 256) {
        float4 v = p[i];
        s += v.x + v.y + v.z + v.w;
    }
    __shared__ float red[256];
    red[threadIdx.x] = s; __syncthreads();
    for (int o = 128; o > 0; o >>= 1) {
        if (threadIdx.x < o) red[threadIdx.x] += red[threadIdx.x + o];
        __syncthreads();
    }
    if (threadIdx.x == 0) g_mean[nc] = red[0] * (1.f / (float)HWI);
}

// ---------------- 2) attention + zero stats ----------------
__global__ void att_kernel(const float* __restrict__ aw_v, const float* __restrict__ ab_v,
                           const float* __restrict__ aw_h, const float* __restrict__ ab_h) {
    int t = threadIdx.x;
    if (t < 64) {
        int dir = t >> 5, n = (t >> 2) & 7, k = t & 3;
        const float* aw = dir ? aw_h : aw_v;
        const float* ab = dir ? ab_h : ab_v;
        const float* m = g_mean + n * C_IN + dir * C_H;
        float s = ab[k];
        #pragma unroll
        for (int ci = 0; ci < C_H; ci++) s += m[ci] * aw[k * C_H + ci];
        g_att[t] = 1.f / (1.f + expf(-s));
    }
    if (t < 128) g_stats[t] = 0.f;
}

// ---------------- 3) weight prep ----------------
__global__ void prep_kernel(const float* __restrict__ sq_w,
                            const float* __restrict__ w_v, const float* __restrict__ w_h) {
    int idx = blockIdx.x * 256 + threadIdx.x;
    if (idx < C_IN*9*64) {
        int co = idx & 63, k = (idx >> 6) % 9, ci = idx / 576;
        float w = sq_w[(co * C_IN + ci) * 9 + k];
        int o = (ci * 9 + k) * 128 + co * 2;
        g_sqw[o] = w; g_sqw[o + 1] = w;
    } else if (idx < C_IN*9*64 + 2*24576) {
        int r = idx - C_IN*9*64;
        int dir = r / 24576; r %= 24576;
        int co = r & 31, kh = (r >> 5) % 3, ci = (r / 96) & 31, n = r / 3072;
        const float* w = dir ? w_h : w_v;
        const float* att = &g_att[dir * 32 + n * 4];
        float v = 0.f;
        #pragma unroll
        for (int k = 0; k < 4; k++) v += att[k] * w[((k * 32 + co) * 32 + ci) * 3 + kh];
        float* dst = dir ? g_wh : g_wv;
        int o = ((n * 32 + ci) * 3 + kh) * 64 + co * 2;
        dst[o] = v; dst[o + 1] = v;
    }
}

// ---------------- 4) square 3x3 s2 conv ----------------
// 32 out-x * 4 out-y * 64 co per block; thread = 2x(packed) * 2y * 8co.
// Inputs deinterleaved into SE (even cols), SO (odd cols), SE2 (even shifted by 1)
// so each kw tap is one aligned LDS.64 — no packing MOVs.
__global__ void __launch_bounds__(256, 3)
sq_kernel(const float* __restrict__ x, const float* __restrict__ sq_b, float* __restrict__ out) {
    __shared__ __align__(16) float sE [4*9*34];
    __shared__ __align__(16) float sO [4*9*34];
    __shared__ __align__(16) float sE2[4*9*34];
    __shared__ __align__(16) float s_w[4*9*128];
    const int tid = threadIdx.x;
    const int tx = tid & 15, ty = (tid >> 4) & 1, tc = tid >> 5;
    const int x0 = blockIdx.x * 32, y0 = blockIdx.y * 4, n = blockIdx.z;
    const int gx0 = 2*x0 - 1, gy0 = 2*y0 - 1;
    const int lane8 = tid & 7, rt = tid >> 3;   // loader: 8 threads per row-task

    ull acc[2][8];
    #pragma unroll
    for (int a = 0; a < 2; a++)
        #pragma unroll
        for (int b = 0; b < 8; b++) acc[a][b] = 0ULL;

    for (int ci0 = 0; ci0 < C_IN; ci0 += 4) {
        __syncthreads();
        // input: 36 row-tasks (4 ci x 9 rows), 65 cols each, deinterleaved
        #pragma unroll
        for (int pass = 0; pass < 2; pass++) {
            int row = rt + pass * 32;
            if (row < 36) {
                int ci = row / 9, r = row - ci * 9;
                int gy = gy0 + r;
                const float* src = x + ((size_t)(n * C_IN + ci0 + ci) * HI + gy) * WI + gx0;
                float* pe  = &sE [(ci * 9 + r) * 34];
                float* po  = &sO [(ci * 9 + r) * 34];
                float* pe2 = &sE2[(ci * 9 + r) * 34];
                bool vy = (gy >= 0);
                #pragma unroll
                for (int c = lane8; c < 65; c += 8) {
                    int gx = gx0 + c;
                    float v = (vy && gx >= 0) ? src[c] : 0.f;
                    int h = c >> 1;
                    if (c & 1) po[h] = v;
                    else { pe[h] = v; if (h) pe2[h - 1] = v; }
                }
            }
        }
        // weights: 1152 float4
        {
            const float4* src = (const float4*)(g_sqw + ci0 * 9 * 128);
            float4* dst = (float4*)s_w;
            #pragma unroll
            for (int i = 0; i < 5; i++) {
                int k = tid + i * 256;
                if (k < 1152) dst[k] = src[k];
            }
        }
        __syncthreads();

        #pragma unroll
        for (int ci = 0; ci < 4; ci++) {
            #pragma unroll
            for (int kh = 0; kh < 3; kh++) {
                const int r0 = 4 * ty + kh;
                const int o0 = (ci * 9 + r0) * 34 + 2 * tx;
                const int o1 = o0 + 2 * 34;
                ull p0[3] = { *(const ull*)&sE[o0], *(const ull*)&sO[o0], *(const ull*)&sE2[o0] };
                ull p1[3] = { *(const ull*)&sE[o1], *(const ull*)&sO[o1], *(const ull*)&sE2[o1] };
                #pragma unroll
                for (int kw = 0; kw < 3; kw++) {
                    const float* wp = &s_w[(ci * 9 + kh * 3 + kw) * 128 + tc * 16];
                    ulonglong2 wA = *(const ulonglong2*)(wp);
                    ulonglong2 wB = *(const ulonglong2*)(wp + 4);
                    ulonglong2 wC = *(const ulonglong2*)(wp + 8);
                    ulonglong2 wD = *(const ulonglong2*)(wp + 12);
                    ffma2(acc[0][0], p0[kw], wA.x); ffma2(acc[0][1], p0[kw], wA.y);
                    ffma2(acc[0][2], p0[kw], wB.x); ffma2(acc[0][3], p0[kw], wB.y);
                    ffma2(acc[0][4], p0[kw], wC.x); ffma2(acc[0][5], p0[kw], wC.y);
                    ffma2(acc[0][6], p0[kw], wD.x); ffma2(acc[0][7], p0[kw], wD.y);
                    ffma2(acc[1][0], p1[kw], wA.x); ffma2(acc[1][1], p1[kw], wA.y);
                    ffma2(acc[1][2], p1[kw], wB.x); ffma2(acc[1][3], p1[kw], wB.y);
                    ffma2(acc[1][4], p1[kw], wC.x); ffma2(acc[1][5], p1[kw], wC.y);
                    ffma2(acc[1][6], p1[kw], wD.x); ffma2(acc[1][7], p1[kw], wD.y);
                }
            }
        }
    }
    // bias + channel shuffle
    #pragma unroll
    for (int j = 0; j < 8; j++) {
        int co = tc * 8 + j;
        float bias = sq_b[co];
        int oc = ((co & 15) << 3) + (co >> 4);
        #pragma unroll
        for (int yy = 0; yy < 2; yy++) {
            int y = y0 + 2 * ty + yy;
            float lo, hi; unpack2(acc[yy][j], lo, hi);
            *(float2*)&out[((size_t)(n * 128 + oc) * HO + y) * WO + x0 + 2 * tx] =
                make_float2(lo + bias, hi + bias);
        }
    }
}

// ---------------- stats epilogue helper (warp reduce + atomics) ----------------
__device__ __forceinline__ void stats_epilogue(const ull* acc, int dir, int tc, int lid) {
    #pragma unroll
    for (int j = 0; j < 8; j++) {
        float lo, hi; unpack2(acc[j], lo, hi);
        float s = lo + hi;
        float q = lo * lo + hi * hi;
        #pragma unroll
        for (int o = 16; o > 0; o >>= 1) {
            s += __shfl_xor_sync(0xffffffff, s, o);
            q += __shfl_xor_sync(0xffffffff, q, o);
        }
        if (lid == 0) {
            int c = tc * 8 + j;
            atomicAdd(&g_stats[(dir * 32 + c) * 2],     s);
            atomicAdd(&g_stats[(dir * 32 + c) * 2 + 1], q);
        }
    }
}

// ---------------- 5) vertical CondConv (3x1, s2) ----------------
__global__ void __launch_bounds__(256, 3)
v_kernel(const float* __restrict__ x) {
    __shared__ __align__(16) float s_in[16*9*32];
    __shared__ __align__(16) float s_w[16*3*64];
    const int tid = threadIdx.x;
    const int tx = tid & 15, ty = (tid >> 4) & 3, tc = tid >> 6;
    const int x0 = blockIdx.x * 32, y0 = blockIdx.y * 4, n = blockIdx.z;
    const int gy0 = 2*y0 - 1;
    const int lane8 = tid & 7, rt = tid >> 3;
    ull acc[8];
    #pragma unroll
    for (int j = 0; j < 8; j++) acc[j] = 0ULL;

    for (int ci0 = 0; ci0 < C_H; ci0 += 16) {
        __syncthreads();
        // 144 row-tasks (16 ci x 9 rows), 32 even cols each
        for (int row = rt; row < 144; row += 32) {
            int ci = row / 9, r = row - ci * 9;
            int gy = gy0 + r;
            const float* src = x + ((size_t)(n * C_IN + ci0 + ci) * HI + gy) * WI + 2 * x0;
            float* dst = &s_in[(ci * 9 + r) * 32];
            bool vy = (gy >= 0);
            #pragma unroll
            for (int c = lane8; c < 32; c += 8)
                dst[c] = vy ? src[2 * c] : 0.f;
        }
        {
            const float4* src = (const float4*)(g_wv + (size_t)(n * 32 + ci0) * 192);
            float4* dst = (float4*)s_w;
            #pragma unroll
            for (int i = 0; i < 3; i++) dst[tid + i * 256];
            #pragma unroll
            for (int i = 0; i < 3; i++) { int k = tid + i * 256; if (k < 768) dst[k] = src[k]; }
        }
        __syncthreads();
        #pragma unroll
        for (int ci = 0; ci < 16; ci++) {
            #pragma unroll
            for (int kh = 0; kh < 3; kh++) {
                int r = 2 * ty + kh;
                ull in2 = *(const ull*)&s_in[(ci * 9 + r) * 32 + 2 * tx];
                const float* wp = &s_w[(ci * 3 + kh) * 64 + tc * 16];
                ulonglong2 wA = *(const ulonglong2*)(wp);
                ulonglong2 wB = *(const ulonglong2*)(wp + 4);
                ulonglong2 wC = *(const ulonglong2*)(wp + 8);
                ulonglong2 wD = *(const ulonglong2*)(wp + 12);
                ffma2(acc[0], in2, wA.x); ffma2(acc[1], in2, wA.y);
                ffma2(acc[2], in2, wB.x); ffma2(acc[3], in2, wB.y);
                ffma2(acc[4], in2, wC.x); ffma2(acc[5], in2, wC.y);
                ffma2(acc[6], in2, wD.x); ffma2(acc[7], in2, wD.y);
            }
        }
    }
    int y = y0 + ty;
    #pragma unroll
    for (int j = 0; j < 8; j++) {
        int co = tc * 8 + j;
        float lo, hi; unpack2(acc[j], lo, hi);
        *(float2*)&g_vraw[((size_t)(n * 32 + co) * HO + y) * WO + x0 + 2 * tx] =
            make_float2(lo, hi);
    }
    stats_epilogue(acc, 0, tc, tid & 31);
}

// ---------------- 6) horizontal CondConv (1x3, s2) ----------------
__global__ void __launch_bounds__(256, 3)
h_kernel(const float* __restrict__ x) {
    __shared__ __align__(16) float sE [16*4*34];
    __shared__ __align__(16) float sO [16*4*34];
    __shared__ __align__(16) float sE2[16*4*34];
    __shared__ __align__(16) float s_w[16*3*64];
    const int tid = threadIdx.x;
    const int tx = tid & 15, ty = (tid >> 4) & 3, tc = tid >> 6;
    const int x0 = blockIdx.x * 32, y0 = blockIdx.y * 4, n = blockIdx.z;
    const int gx0 = 2*x0 - 1;
    const int lane8 = tid & 7, rt = tid >> 3;
    ull acc[8];
    #pragma unroll
    for (int j = 0; j < 8; j++) acc[j] = 0ULL;

    for (int ci0 = 0; ci0 < C_H; ci0 += 16) {
        __syncthreads();
        // 64 row-tasks (16 ci x 4 even rows), 65 cols, deinterleaved
        #pragma unroll
        for (int pass = 0; pass < 2; pass++) {
            int row = rt + pass * 32;   // 0..63
            int ci = row >> 2, r = row & 3;
            int gy = 2 * (y0 + r);
            const float* src = x + ((size_t)(n * C_IN + C_H + ci0 + ci) * HI + gy) * WI + gx0;
            float* pe  = &sE [(ci * 4 + r) * 34];
            float* po  = &sO [(ci * 4 + r) * 34];
            float* pe2 = &sE2[(ci * 4 + r) * 34];
            #pragma unroll
            for (int c = lane8; c < 65; c += 8) {
                int gx = gx0 + c;
                float v = (gx >= 0) ? src[c] : 0.f;
                int h = c >> 1;
                if (c & 1) po[h] = v;
                else { pe[h] = v; if (h) pe2[h - 1] = v; }
            }
        }
        {
            const float4* src = (const float4*)(g_wh + (size_t)(n * 32 + ci0) * 192);
            float4* dst = (float4*)s_w;
            #pragma unroll
            for (int i = 0; i < 3; i++) { int k = tid + i * 256; if (k < 768) dst[k] = src[k]; }
        }
        __syncthreads();
        #pragma unroll
        for (int ci = 0; ci < 16; ci++) {
            const int o = (ci * 4 + ty) * 34 + 2 * tx;
            ull p[3] = { *(const ull*)&sE[o], *(const ull*)&sO[o], *(const ull*)&sE2[o] };
            #pragma unroll
            for (int kw = 0; kw < 3; kw++) {
                const float* wp = &s_w[(ci * 3 + kw) * 64 + tc * 16];
                ulonglong2 wA = *(const ulonglong2*)(wp);
                ulonglong2 wB = *(const ulonglong2*)(wp + 4);
                ulonglong2 wC = *(const ulonglong2*)(wp + 8);
                ulonglong2 wD = *(const ulonglong2*)(wp + 12);
                ffma2(acc[0], p[kw], wA.x); ffma2(acc[1], p[kw], wA.y);
                ffma2(acc[2], p[kw], wB.x); ffma2(acc[3], p[kw], wB.y);
                ffma2(acc[4], p[kw], wC.x); ffma2(acc[5], p[kw], wC.y);
                ffma2(acc[6], p[kw], wD.x); ffma2(acc[7], p[kw], wD.y);
            }
        }
    }
    int y = y0 + ty;
    #pragma unroll
    for (int j = 0; j < 8; j++) {
        int co = tc * 8 + j;
        float lo, hi; unpack2(acc[j], lo, hi);
        *(float2*)&g_hraw[((size_t)(n * 32 + co) * HO + y) * WO + x0 + 2 * tx] =
            make_float2(lo, hi);
    }
    stats_epilogue(acc, 1, tc, tid & 31);
}

// ---------------- 7) BN apply + shuffle ----------------
__global__ void bn_kernel(const float* __restrict__ gv, const float* __restrict__ bv,
                          const float* __restrict__ gh, const float* __restrict__ bh,
                          float* __restrict__ out) {
    int bid = blockIdx.x;
    int dir = bid >> 8, co = (bid >> 3) & 31, n = bid & 7;
    float sum = g_stats[(dir * 32 + co) * 2];
    float sq  = g_stats[(dir * 32 + co) * 2 + 1];
    const float inv = 1.f / (float)NPIX_CH;
    float m = sum * inv;
    float var = sq * inv - m * m;
    float gam = (dir ? gh : gv)[co];
    float bet = (dir ? bh : bv)[co];
    float scale = gam * rsqrtf(var + 1e-5f);
    float shift = bet - m * scale;
    int oc = ((co & 15) << 3) + 4 + 2 * dir + (co >> 4);
    const float4* src = (const float4*)((dir ? g_hraw : g_vraw) + (size_t)(n * 32 + co) * HWO);
    float4* dst = (float4*)(out + (size_t)(n * 128 + oc) * HWO);
    for (int i = threadIdx.x; i < 9216; i += 256) {
        float4 v = src[i];
        v.x = v.x * scale + shift; v.y = v.y * scale + shift;
        v.z = v.z * scale + shift; v.w = v.w * scale + shift;
        dst[i] = v;
    }
}

// ---------------- launch ----------------
extern "C" void kernel_launch(void* const* d_in, const int* in_sizes, int n_in,
                              void* d_out, int out_size) {
    const float* x      = (const float*)d_in[0];
    const float* sq_w   = (const float*)d_in[1];
    const float* sq_b   = (const float*)d_in[2];
    const float* aw_v   = (const float*)d_in[3];
    const float* ab_v   = (const float*)d_in[4];
    const float* w_v    = (const float*)d_in[5];
    const float* bn_v_g = (const float*)d_in[6];
    const float* bn_v_b = (const float*)d_in[7];
    const float* aw_h   = (const float*)d_in[8];
    const float* ab_h   = (const float*)d_in[9];
    const float* w_h    = (const float*)d_in[10];
    const float* bn_h_g = (const float*)d_in[11];
    const float* bn_h_b = (const float*)d_in[12];
    float* out = (float*)d_out;

    mean_kernel<<<N_B * C_IN, 256>>>(x);
    att_kernel<<<1, 128>>>(aw_v, ab_v, aw_h, ab_h);
    prep_kernel<<<336, 256>>>(sq_w, w_v, w_h);
    sq_kernel<<<dim3(WO/32, HO/4, N_B), 256>>>(x, sq_b, out);
    v_kernel<<<dim3(WO/32, HO/4, N_B), 256>>>(x);
    h_kernel<<<dim3(WO/32, HO/4, N_B), 256>>>(x);
    bn_kernel<<<512, 256>>>(bn_v_g, bn_v_b, bn_h_g, bn_h_b, out);
}

// round 4
// speedup vs baseline: 1.1177x; 1.1177x over previous
#include <cuda_runtime.h>
#include <math.h>

typedef unsigned long long ull;

#define N_B 8
#define C_IN 64
#define C_H 32
#define HI 384
#define WI 384
#define HO 192
#define WO 192
#define HWI (HI*WI)
#define HWO (HO*WO)
#define NPIX_CH (N_B*HWO)

// ---------------- scratch ----------------
__device__ float g_mean[N_B*C_IN];
__device__ float g_att[2*N_B*4];
__device__ float g_sqw[C_IN*9*128];          // [ci][k9][co*2 duplicated]
__device__ float g_wv[N_B*C_H*3*64];         // [n][ci][kh][co*2 duplicated]
__device__ float g_wh[N_B*C_H*3*64];
__device__ float g_vraw[(size_t)N_B*C_H*HWO];
__device__ float g_hraw[(size_t)N_B*C_H*HWO];
__device__ float g_stats[2*C_H*2];

// ---------------- f32x2 helpers ----------------
__device__ __forceinline__ ull pack2(float a, float b) {
    ull r; asm("mov.b64 %0, {%1, %2};" : "=l"(r) : "f"(a), "f"(b)); return r;
}
__device__ __forceinline__ void unpack2(ull v, float& a, float& b) {
    asm("mov.b64 {%0, %1}, %2;" : "=f"(a), "=f"(b) : "l"(v));
}
__device__ __forceinline__ void ffma2(ull& d, ull a, ull b) {
    asm("fma.rn.f32x2 %0, %1, %2, %0;" : "+l"(d) : "l"(a), "l"(b));
}

// ---------------- 1) channel means ----------------
__global__ void mean_kernel(const float* __restrict__ x) {
    int nc = blockIdx.x;
    const float4* p = (const float4*)(x + (size_t)nc * HWI);
    float s = 0.f;
    for (int i = threadIdx.x; i < HWI/4; i += 256) {
        float4 v = p[i];
        s += v.x + v.y + v.z + v.w;
    }
    __shared__ float red[256];
    red[threadIdx.x] = s; __syncthreads();
    for (int o = 128; o > 0; o >>= 1) {
        if (threadIdx.x < o) red[threadIdx.x] += red[threadIdx.x + o];
        __syncthreads();
    }
    if (threadIdx.x == 0) g_mean[nc] = red[0] * (1.f / (float)HWI);
}

// ---------------- 2) attention + zero stats ----------------
__global__ void att_kernel(const float* __restrict__ aw_v, const float* __restrict__ ab_v,
                           const float* __restrict__ aw_h, const float* __restrict__ ab_h) {
    int t = threadIdx.x;
    if (t < 64) {
        int dir = t >> 5, n = (t >> 2) & 7, k = t & 3;
        const float* aw = dir ? aw_h : aw_v;
        const float* ab = dir ? ab_h : ab_v;
        const float* m = g_mean + n * C_IN + dir * C_H;
        float s = ab[k];
        #pragma unroll
        for (int ci = 0; ci < C_H; ci++) s += m[ci] * aw[k * C_H + ci];
        g_att[t] = 1.f / (1.f + expf(-s));
    }
    if (t < 128) g_stats[t] = 0.f;
}

// ---------------- 3) weight prep ----------------
__global__ void prep_kernel(const float* __restrict__ sq_w,
                            const float* __restrict__ w_v, const float* __restrict__ w_h) {
    int idx = blockIdx.x * 256 + threadIdx.x;
    if (idx < C_IN*9*64) {
        int co = idx & 63, k = (idx >> 6) % 9, ci = idx / 576;
        float w = sq_w[(co * C_IN + ci) * 9 + k];
        int o = (ci * 9 + k) * 128 + co * 2;
        g_sqw[o] = w; g_sqw[o + 1] = w;
    } else if (idx < C_IN*9*64 + 2*24576) {
        int r = idx - C_IN*9*64;
        int dir = r / 24576; r %= 24576;
        int co = r & 31, kh = (r >> 5) % 3, ci = (r / 96) & 31, n = r / 3072;
        const float* w = dir ? w_h : w_v;
        const float* att = &g_att[dir * 32 + n * 4];
        float v = 0.f;
        #pragma unroll
        for (int k = 0; k < 4; k++) v += att[k] * w[((k * 32 + co) * 32 + ci) * 3 + kh];
        float* dst = dir ? g_wh : g_wv;
        int o = ((n * 32 + ci) * 3 + kh) * 64 + co * 2;
        dst[o] = v; dst[o + 1] = v;
    }
}

// ---------------- 4) square 3x3 s2 conv ----------------
// Block: 64 out-x * 4 out-y * 64 co. Thread (tx16, ty2, tc8):
//   x = x0 + 4*tx .. +3 (2 packed pairs via one LDS.128 per E/O/E2 array),
//   y = y0 + 2*ty + {0,1},  co = tc*8 .. +7.
// 32 f32x2 accumulators per thread; 18 LDS per 96 FFMA2.
__global__ void __launch_bounds__(256)
sq_kernel(const float* __restrict__ x, const float* __restrict__ sq_b, float* __restrict__ out) {
    __shared__ __align__(16) float sE [4*9*68];   // E[h]  = in col 2h      (h 0..64)
    __shared__ __align__(16) float sO [4*9*68];   // O[h]  = in col 2h+1    (h 0..63)
    __shared__ __align__(16) float sE2[4*9*68];   // E2[h] = in col 2h+2    (h 0..63)
    __shared__ __align__(16) float s_w[4*9*128];
    const int tid = threadIdx.x;
    const int tx = tid & 15, ty = (tid >> 4) & 1, tc = tid >> 5;
    const int lane = tid & 31, wid = tid >> 5;
    const int x0 = blockIdx.x * 64, y0 = blockIdx.y * 4, n = blockIdx.z;
    const int gx0 = 2*x0 - 1, gy0 = 2*y0 - 1;

    ull acc[2][2][8];   // [yy][pair][co]
    #pragma unroll
    for (int a = 0; a < 2; a++)
        #pragma unroll
        for (int b = 0; b < 2; b++)
            #pragma unroll
            for (int j = 0; j < 8; j++) acc[a][b][j] = 0ULL;

    for (int ci0 = 0; ci0 < C_IN; ci0 += 4) {
        __syncthreads();
        // input: 36 row-tasks (4 ci x 9 rows), 129 cols, one warp per row (coalesced)
        for (int row = wid; row < 36; row += 8) {
            int ci = row / 9, r = row - ci * 9;
            int gy = gy0 + r;
            const float* src = x + ((size_t)(n * C_IN + ci0 + ci) * HI + gy) * WI + gx0;
            float* pe  = &sE [(ci * 9 + r) * 68];
            float* po  = &sO [(ci * 9 + r) * 68];
            float* pe2 = &sE2[(ci * 9 + r) * 68];
            bool vy = (gy >= 0);
            #pragma unroll
            for (int c = lane; c < 129; c += 32) {
                int gx = gx0 + c;
                float v = (vy && gx >= 0) ? src[c] : 0.f;
                int h = c >> 1;
                if (c & 1) po[h] = v;
                else { pe[h] = v; if (h) pe2[h - 1] = v; }
            }
        }
        // weights: 1152 float4
        {
            const float4* src = (const float4*)(g_sqw + ci0 * 9 * 128);
            float4* dst = (float4*)s_w;
            #pragma unroll
            for (int i = 0; i < 5; i++) {
                int k = tid + i * 256;
                if (k < 1152) dst[k] = src[k];
            }
        }
        __syncthreads();

        #pragma unroll
        for (int ci = 0; ci < 4; ci++) {
            #pragma unroll
            for (int kh = 0; kh < 3; kh++) {
                const int rA = 4 * ty + kh;           // y row 0 of this lane
                const int oA = (ci * 9 + rA) * 68 + 4 * tx;
                const int oB = oA + 2 * 68;           // y row 1
                ulonglong2 inA[3], inB[3];            // [kw]: .x = pair0, .y = pair1
                inA[0] = *(const ulonglong2*)&sE [oA];
                inA[1] = *(const ulonglong2*)&sO [oA];
                inA[2] = *(const ulonglong2*)&sE2[oA];
                inB[0] = *(const ulonglong2*)&sE [oB];
                inB[1] = *(const ulonglong2*)&sO [oB];
                inB[2] = *(const ulonglong2*)&sE2[oB];
                #pragma unroll
                for (int kw = 0; kw < 3; kw++) {
                    const float* wp = &s_w[(ci * 9 + kh * 3 + kw) * 128 + tc * 16];
                    ulonglong2 wA = *(const ulonglong2*)(wp);
                    ulonglong2 wB = *(const ulonglong2*)(wp + 4);
                    ulonglong2 wC = *(const ulonglong2*)(wp + 8);
                    ulonglong2 wD = *(const ulonglong2*)(wp + 12);
                    ffma2(acc[0][0][0], inA[kw].x, wA.x); ffma2(acc[0][0][1], inA[kw].x, wA.y);
                    ffma2(acc[0][0][2], inA[kw].x, wB.x); ffma2(acc[0][0][3], inA[kw].x, wB.y);
                    ffma2(acc[0][0][4], inA[kw].x, wC.x); ffma2(acc[0][0][5], inA[kw].x, wC.y);
                    ffma2(acc[0][0][6], inA[kw].x, wD.x); ffma2(acc[0][0][7], inA[kw].x, wD.y);
                    ffma2(acc[0][1][0], inA[kw].y, wA.x); ffma2(acc[0][1][1], inA[kw].y, wA.y);
                    ffma2(acc[0][1][2], inA[kw].y, wB.x); ffma2(acc[0][1][3], inA[kw].y, wB.y);
                    ffma2(acc[0][1][4], inA[kw].y, wC.x); ffma2(acc[0][1][5], inA[kw].y, wC.y);
                    ffma2(acc[0][1][6], inA[kw].y, wD.x); ffma2(acc[0][1][7], inA[kw].y, wD.y);
                    ffma2(acc[1][0][0], inB[kw].x, wA.x); ffma2(acc[1][0][1], inB[kw].x, wA.y);
                    ffma2(acc[1][0][2], inB[kw].x, wB.x); ffma2(acc[1][0][3], inB[kw].x, wB.y);
                    ffma2(acc[1][0][4], inB[kw].x, wC.x); ffma2(acc[1][0][5], inB[kw].x, wC.y);
                    ffma2(acc[1][0][6], inB[kw].x, wD.x); ffma2(acc[1][0][7], inB[kw].x, wD.y);
                    ffma2(acc[1][1][0], inB[kw].y, wA.x); ffma2(acc[1][1][1], inB[kw].y, wA.y);
                    ffma2(acc[1][1][2], inB[kw].y, wB.x); ffma2(acc[1][1][3], inB[kw].y, wB.y);
                    ffma2(acc[1][1][4], inB[kw].y, wC.x); ffma2(acc[1][1][5], inB[kw].y, wC.y);
                    ffma2(acc[1][1][6], inB[kw].y, wD.x); ffma2(acc[1][1][7], inB[kw].y, wD.y);
                }
            }
        }
    }
    // epilogue: bias + channel shuffle, float4 stores
    #pragma unroll
    for (int j = 0; j < 8; j++) {
        int co = tc * 8 + j;
        float bias = sq_b[co];
        int oc = ((co & 15) << 3) + (co >> 4);
        #pragma unroll
        for (int yy = 0; yy < 2; yy++) {
            int y = y0 + 2 * ty + yy;
            float4 o;
            unpack2(acc[yy][0][j], o.x, o.y);
            unpack2(acc[yy][1][j], o.z, o.w);
            o.x += bias; o.y += bias; o.z += bias; o.w += bias;
            *(float4*)&out[((size_t)(n * 128 + oc) * HO + y) * WO + x0 + 4 * tx] = o;
        }
    }
}

// ---------------- 5) vertical CondConv (3x1, s2) -> g_vraw ----------------
__global__ void __launch_bounds__(256)
v_kernel(const float* __restrict__ x) {
    __shared__ __align__(16) float s_in[16*9*32];
    __shared__ __align__(16) float s_w[16*3*64];
    const int tid = threadIdx.x;
    const int tx = tid & 15, ty = (tid >> 4) & 3, tc = tid >> 6;
    const int x0 = blockIdx.x * 32, y0 = blockIdx.y * 4, n = blockIdx.z;
    const int gy0 = 2*y0 - 1;
    ull acc[8];
    #pragma unroll
    for (int j = 0; j < 8; j++) acc[j] = 0ULL;

    for (int ci0 = 0; ci0 < C_H; ci0 += 16) {
        __syncthreads();
        for (int i = tid; i < 16*9*32; i += 256) {
            int c = i & 31, r = (i >> 5) % 9, ci = i / 288;
            int gy = gy0 + r;
            float v = 0.f;
            if (gy >= 0)
                v = x[((size_t)(n * C_IN + ci0 + ci) * HI + gy) * WI + 2 * (x0 + c)];
            s_in[(ci * 9 + r) * 32 + c] = v;
        }
        {
            const float4* src = (const float4*)(g_wv + (size_t)(n * 32 + ci0) * 192);
            float4* dst = (float4*)s_w;
            for (int i = tid; i < 768; i += 256) dst[i] = src[i];
        }
        __syncthreads();
        #pragma unroll
        for (int ci = 0; ci < 16; ci++) {
            #pragma unroll
            for (int kh = 0; kh < 3; kh++) {
                int r = 2 * ty + kh;
                ull in2 = *(const ull*)&s_in[(ci * 9 + r) * 32 + 2 * tx];
                const float* wp = &s_w[(ci * 3 + kh) * 64 + tc * 16];
                ulonglong2 wA = *(const ulonglong2*)(wp);
                ulonglong2 wB = *(const ulonglong2*)(wp + 4);
                ulonglong2 wC = *(const ulonglong2*)(wp + 8);
                ulonglong2 wD = *(const ulonglong2*)(wp + 12);
                ffma2(acc[0], in2, wA.x); ffma2(acc[1], in2, wA.y);
                ffma2(acc[2], in2, wB.x); ffma2(acc[3], in2, wB.y);
                ffma2(acc[4], in2, wC.x); ffma2(acc[5], in2, wC.y);
                ffma2(acc[6], in2, wD.x); ffma2(acc[7], in2, wD.y);
            }
        }
    }
    int y = y0 + ty;
    #pragma unroll
    for (int j = 0; j < 8; j++) {
        int co = tc * 8 + j;
        float lo, hi; unpack2(acc[j], lo, hi);
        *(float2*)&g_vraw[((size_t)(n * 32 + co) * HO + y) * WO + x0 + 2 * tx] =
            make_float2(lo, hi);
    }
}

// ---------------- 6) horizontal CondConv (1x3, s2) -> g_hraw ----------------
__global__ void __launch_bounds__(256)
h_kernel(const float* __restrict__ x) {
    __shared__ __align__(16) float sE [16*4*34];
    __shared__ __align__(16) float sO [16*4*34];
    __shared__ __align__(16) float sE2[16*4*34];
    __shared__ __align__(16) float s_w[16*3*64];
    const int tid = threadIdx.x;
    const int tx = tid & 15, ty = (tid >> 4) & 3, tc = tid >> 6;
    const int x0 = blockIdx.x * 32, y0 = blockIdx.y * 4, n = blockIdx.z;
    const int gx0 = 2*x0 - 1;
    const int lane8 = tid & 7, rt = tid >> 3;
    ull acc[8];
    #pragma unroll
    for (int j = 0; j < 8; j++) acc[j] = 0ULL;

    for (int ci0 = 0; ci0 < C_H; ci0 += 16) {
        __syncthreads();
        #pragma unroll
        for (int pass = 0; pass < 2; pass++) {
            int row = rt + pass * 32;   // 0..63
            int ci = row >> 2, r = row & 3;
            int gy = 2 * (y0 + r);
            const float* src = x + ((size_t)(n * C_IN + C_H + ci0 + ci) * HI + gy) * WI + gx0;
            float* pe  = &sE [(ci * 4 + r) * 34];
            float* po  = &sO [(ci * 4 + r) * 34];
            float* pe2 = &sE2[(ci * 4 + r) * 34];
            #pragma unroll
            for (int c = lane8; c < 65; c += 8) {
                int gx = gx0 + c;
                float v = (gx >= 0) ? src[c] : 0.f;
                int h = c >> 1;
                if (c & 1) po[h] = v;
                else { pe[h] = v; if (h) pe2[h - 1] = v; }
            }
        }
        {
            const float4* src = (const float4*)(g_wh + (size_t)(n * 32 + ci0) * 192);
            float4* dst = (float4*)s_w;
            #pragma unroll
            for (int i = 0; i < 3; i++) { int k = tid + i * 256; if (k < 768) dst[k] = src[k]; }
        }
        __syncthreads();
        #pragma unroll
        for (int ci = 0; ci < 16; ci++) {
            const int o = (ci * 4 + ty) * 34 + 2 * tx;
            ull p[3] = { *(const ull*)&sE[o], *(const ull*)&sO[o], *(const ull*)&sE2[o] };
            #pragma unroll
            for (int kw = 0; kw < 3; kw++) {
                const float* wp = &s_w[(ci * 3 + kw) * 64 + tc * 16];
                ulonglong2 wA = *(const ulonglong2*)(wp);
                ulonglong2 wB = *(const ulonglong2*)(wp + 4);
                ulonglong2 wC = *(const ulonglong2*)(wp + 8);
                ulonglong2 wD = *(const ulonglong2*)(wp + 12);
                ffma2(acc[0], p[kw], wA.x); ffma2(acc[1], p[kw], wA.y);
                ffma2(acc[2], p[kw], wB.x); ffma2(acc[3], p[kw], wB.y);
                ffma2(acc[4], p[kw], wC.x); ffma2(acc[5], p[kw], wC.y);
                ffma2(acc[6], p[kw], wD.x); ffma2(acc[7], p[kw], wD.y);
            }
        }
    }
    int y = y0 + ty;
    #pragma unroll
    for (int j = 0; j < 8; j++) {
        int co = tc * 8 + j;
        float lo, hi; unpack2(acc[j], lo, hi);
        *(float2*)&g_hraw[((size_t)(n * 32 + co) * HO + y) * WO + x0 + 2 * tx] =
            make_float2(lo, hi);
    }
}

// ---------------- 7) BN statistics ----------------
__global__ void stats_kernel() {
    int bid = blockIdx.x;
    int dir = bid >> 7, c = (bid >> 2) & 31, sl = bid & 3;
    const float* base = dir ? g_hraw : g_vraw;
    float s = 0.f, q = 0.f;
    for (int i = threadIdx.x; i < 18432; i += 256) {
        int e4 = sl * 18432 + i;
        int n = e4 / 9216, ri = e4 % 9216;
        float4 v = ((const float4*)(base + (size_t)(n * 32 + c) * HWO))[ri];
        s += v.x + v.y + v.z + v.w;
        q += v.x * v.x + v.y * v.y + v.z * v.z + v.w * v.w;
    }
    __shared__ float red[512];
    red[threadIdx.x] = s; red[256 + threadIdx.x] = q;
    __syncthreads();
    for (int o = 128; o > 0; o >>= 1) {
        if (threadIdx.x < o) {
            red[threadIdx.x] += red[threadIdx.x + o];
            red[256 + threadIdx.x] += red[256 + threadIdx.x + o];
        }
        __syncthreads();
    }
    if (threadIdx.x == 0) {
        atomicAdd(&g_stats[(dir * 32 + c) * 2],     red[0]);
        atomicAdd(&g_stats[(dir * 32 + c) * 2 + 1], red[256]);
    }
}

// ---------------- 8) BN apply + shuffle ----------------
__global__ void bn_kernel(const float* __restrict__ gv, const float* __restrict__ bv,
                          const float* __restrict__ gh, const float* __restrict__ bh,
                          float* __restrict__ out) {
    int bid = blockIdx.x;
    int dir = bid >> 8, co = (bid >> 3) & 31, n = bid & 7;
    float sum = g_stats[(dir * 32 + co) * 2];
    float sq  = g_stats[(dir * 32 + co) * 2 + 1];
    const float inv = 1.f / (float)NPIX_CH;
    float m = sum * inv;
    float var = sq * inv - m * m;
    float gam = (dir ? gh : gv)[co];
    float bet = (dir ? bh : bv)[co];
    float scale = gam * rsqrtf(var + 1e-5f);
    float shift = bet - m * scale;
    int oc = ((co & 15) << 3) + 4 + 2 * dir + (co >> 4);
    const float4* src = (const float4*)((dir ? g_hraw : g_vraw) + (size_t)(n * 32 + co) * HWO);
    float4* dst = (float4*)(out + (size_t)(n * 128 + oc) * HWO);
    for (int i = threadIdx.x; i < 9216; i += 256) {
        float4 v = src[i];
        v.x = v.x * scale + shift; v.y = v.y * scale + shift;
        v.z = v.z * scale + shift; v.w = v.w * scale + shift;
        dst[i] = v;
    }
}

// ---------------- launch ----------------
extern "C" void kernel_launch(void* const* d_in, const int* in_sizes, int n_in,
                              void* d_out, int out_size) {
    const float* x      = (const float*)d_in[0];
    const float* sq_w   = (const float*)d_in[1];
    const float* sq_b   = (const float*)d_in[2];
    const float* aw_v   = (const float*)d_in[3];
    const float* ab_v   = (const float*)d_in[4];
    const float* w_v    = (const float*)d_in[5];
    const float* bn_v_g = (const float*)d_in[6];
    const float* bn_v_b = (const float*)d_in[7];
    const float* aw_h   = (const float*)d_in[8];
    const float* ab_h   = (const float*)d_in[9];
    const float* w_h    = (const float*)d_in[10];
    const float* bn_h_g = (const float*)d_in[11];
    const float* bn_h_b = (const float*)d_in[12];
    float* out = (float*)d_out;

    mean_kernel<<<N_B * C_IN, 256>>>(x);
    att_kernel<<<1, 128>>>(aw_v, ab_v, aw_h, ab_h);
    prep_kernel<<<336, 256>>>(sq_w, w_v, w_h);
    sq_kernel<<<dim3(WO/64, HO/4, N_B), 256>>>(x, sq_b, out);
    v_kernel<<<dim3(WO/32, HO/4, N_B), 256>>>(x);
    h_kernel<<<dim3(WO/32, HO/4, N_B), 256>>>(x);
    stats_kernel<<<256, 256>>>();
    bn_kernel<<<512, 256>>>(bn_v_g, bn_v_b, bn_h_g, bn_h_b, out);
}

// round 5
// speedup vs baseline: 1.5371x; 1.3753x over previous
#include <cuda_runtime.h>
#include <math.h>

typedef unsigned long long ull;
typedef unsigned int uint;

#define N_B 8
#define C_IN 64
#define C_H 32
#define HI 384
#define WI 384
#define HO 192
#define WO 192
#define HWI (HI*WI)
#define HWO (HO*WO)
#define NPIX_CH (N_B*HWO)

// ---------------- scratch ----------------
__device__ float g_mean[N_B*C_IN];
__device__ float g_att[2*N_B*4];
__device__ float g_sqw[C_IN*9*128];          // [ci][k9][co*2 duplicated]
__device__ float g_wv[N_B*C_H*3*64];         // [n][ci][kh][co*2 duplicated]
__device__ float g_wh[N_B*C_H*3*64];
__device__ float g_vraw[(size_t)N_B*C_H*HWO];
__device__ float g_hraw[(size_t)N_B*C_H*HWO];
__device__ float g_stats[2*C_H*2];

// ---------------- helpers ----------------
__device__ __forceinline__ void unpack2(ull v, float& a, float& b) {
    asm("mov.b64 {%0, %1}, %2;" : "=f"(a), "=f"(b) : "l"(v));
}
__device__ __forceinline__ void ffma2(ull& d, ull a, ull b) {
    asm("fma.rn.f32x2 %0, %1, %2, %0;" : "+l"(d) : "l"(a), "l"(b));
}
__device__ __forceinline__ uint smem_u32(const void* p) {
    uint a; asm("{ .reg .u64 t; cvta.to.shared.u64 t, %1; cvt.u32.u64 %0, t; }" : "=r"(a) : "l"(p));
    return a;
}
__device__ __forceinline__ void cp4(uint dst, const float* src, uint sz) {
    asm volatile("{ .reg .u64 g; cvta.to.global.u64 g, %1;"
                 " cp.async.ca.shared.global [%0], [g], 4, %2; }"
                 :: "r"(dst), "l"(src), "r"(sz) : "memory");
}
__device__ __forceinline__ void cp16(uint dst, const void* src) {
    asm volatile("{ .reg .u64 g; cvta.to.global.u64 g, %1;"
                 " cp.async.cg.shared.global [%0], [g], 16; }"
                 :: "r"(dst), "l"(src) : "memory");
}
#define CP_COMMIT() asm volatile("cp.async.commit_group;" ::: "memory")
#define CP_WAIT(n)  asm volatile("cp.async.wait_group %0;" :: "n"(n) : "memory")

// ---------------- 1) channel means ----------------
__global__ void mean_kernel(const float* __restrict__ x) {
    int nc = blockIdx.x;
    const float4* p = (const float4*)(x + (size_t)nc * HWI);
    float s = 0.f;
    for (int i = threadIdx.x; i < HWI/4; i += 256) {
        float4 v = p[i];
        s += v.x + v.y + v.z + v.w;
    }
    __shared__ float red[256];
    red[threadIdx.x] = s; __syncthreads();
    for (int o = 128; o > 0; o >>= 1) {
        if (threadIdx.x < o) red[threadIdx.x] += red[threadIdx.x + o];
        __syncthreads();
    }
    if (threadIdx.x == 0) g_mean[nc] = red[0] * (1.f / (float)HWI);
}

// ---------------- 2) attention + zero stats ----------------
__global__ void att_kernel(const float* __restrict__ aw_v, const float* __restrict__ ab_v,
                           const float* __restrict__ aw_h, const float* __restrict__ ab_h) {
    int t = threadIdx.x;
    if (t < 64) {
        int dir = t >> 5, n = (t >> 2) & 7, k = t & 3;
        const float* aw = dir ? aw_h : aw_v;
        const float* ab = dir ? ab_h : ab_v;
        const float* m = g_mean + n * C_IN + dir * C_H;
        float s = ab[k];
        #pragma unroll
        for (int ci = 0; ci < C_H; ci++) s += m[ci] * aw[k * C_H + ci];
        g_att[t] = 1.f / (1.f + expf(-s));
    }
    if (t < 128) g_stats[t] = 0.f;
}

// ---------------- 3) weight prep ----------------
__global__ void prep_kernel(const float* __restrict__ sq_w,
                            const float* __restrict__ w_v, const float* __restrict__ w_h) {
    int idx = blockIdx.x * 256 + threadIdx.x;
    if (idx < C_IN*9*64) {
        int co = idx & 63, k = (idx >> 6) % 9, ci = idx / 576;
        float w = sq_w[(co * C_IN + ci) * 9 + k];
        int o = (ci * 9 + k) * 128 + co * 2;
        g_sqw[o] = w; g_sqw[o + 1] = w;
    } else if (idx < C_IN*9*64 + 2*24576) {
        int r = idx - C_IN*9*64;
        int dir = r / 24576; r %= 24576;
        int co = r & 31, kh = (r >> 5) % 3, ci = (r / 96) & 31, n = r / 3072;
        const float* w = dir ? w_h : w_v;
        const float* att = &g_att[dir * 32 + n * 4];
        float v = 0.f;
        #pragma unroll
        for (int k = 0; k < 4; k++) v += att[k] * w[((k * 32 + co) * 32 + ci) * 3 + kh];
        float* dst = dir ? g_wh : g_wv;
        int o = ((n * 32 + ci) * 3 + kh) * 64 + co * 2;
        dst[o] = v; dst[o + 1] = v;
    }
}

// ---------------- 4) square 3x3 s2 conv — cp.async double-buffered ----------------
// Block: 64 out-x * 4 out-y * 64 co. Thread (tx16, ty2, tc8):
//   x = x0+4*tx..+3 (2 packed pairs), y = y0+2*ty+{0,1}, co = tc*8..+7.
// Stage (floats): E[4*9*68] O[4*9*68] E2[4*9*68] W[4*9*128]; two stages.
#define SQ_E   0
#define SQ_O   2448
#define SQ_E2  4896
#define SQ_W   7344
#define SQ_ST  11952
#define SQ_SMEM_BYTES (2*SQ_ST*4)

__global__ void __launch_bounds__(256, 2)
sq_kernel(const float* __restrict__ x, const float* __restrict__ sq_b, float* __restrict__ out) {
    extern __shared__ float sm[];
    const int tid = threadIdx.x;
    const int tx = tid & 15, ty = (tid >> 4) & 1, tc = tid >> 5;
    const int lane = tid & 31, wid = tid >> 5;
    const int x0 = blockIdx.x * 64, y0 = blockIdx.y * 4, n = blockIdx.z;
    const int gx0 = 2*x0 - 1, gy0 = 2*y0 - 1;
    const uint sbase = smem_u32(sm);

    ull acc[2][2][8];   // [yy][pair][co]
    #pragma unroll
    for (int a = 0; a < 2; a++)
        #pragma unroll
        for (int b = 0; b < 2; b++)
            #pragma unroll
            for (int j = 0; j < 8; j++) acc[a][b][j] = 0ULL;

    auto load_chunk = [&](int ci0, int stage) {
        uint st = sbase + (uint)stage * (SQ_ST * 4);
        for (int row = wid; row < 36; row += 8) {
            int ci = row / 9, r = row - ci * 9;
            int gy = gy0 + r;
            const float* src = x + ((size_t)(n * C_IN + ci0 + ci) * HI + gy) * WI + gx0;
            bool vy = (gy >= 0);
            uint ro = st + (uint)(ci * 9 + r) * 68 * 4;
            for (int c = lane; c < 129; c += 32) {
                int gx = gx0 + c;
                bool ok = vy && (gx >= 0);
                uint sz = ok ? 4u : 0u;
                const float* s = ok ? src + c : x;
                int h = c >> 1;
                if (c & 1) {
                    cp4(ro + SQ_O * 4 + h * 4, s, sz);
                } else {
                    cp4(ro + SQ_E * 4 + h * 4, s, sz);
                    if (h) cp4(ro + SQ_E2 * 4 + (h - 1) * 4, s, sz);
                }
            }
        }
        const float4* wsrc = (const float4*)(g_sqw + ci0 * 9 * 128);
        uint wb = st + SQ_W * 4;
        #pragma unroll
        for (int i = 0; i < 5; i++) {
            int k = tid + i * 256;
            if (k < 1152) cp16(wb + k * 16, wsrc + k);
        }
    };

    load_chunk(0, 0);
    CP_COMMIT();

    for (int ch = 0; ch < 16; ch++) {
        if (ch < 15) {
            load_chunk((ch + 1) * 4, (ch + 1) & 1);
            CP_COMMIT();
            CP_WAIT(1);
        } else {
            CP_WAIT(0);
        }
        __syncthreads();

        const float* sE  = sm + (ch & 1) * SQ_ST + SQ_E;
        const float* sO  = sm + (ch & 1) * SQ_ST + SQ_O;
        const float* sE2 = sm + (ch & 1) * SQ_ST + SQ_E2;
        const float* sW  = sm + (ch & 1) * SQ_ST + SQ_W;

        #pragma unroll
        for (int ci = 0; ci < 4; ci++) {
            #pragma unroll
            for (int kh = 0; kh < 3; kh++) {
                const int rA = 4 * ty + kh;
                const int oA = (ci * 9 + rA) * 68 + 4 * tx;
                const int oB = oA + 2 * 68;
                ulonglong2 inA[3], inB[3];
                inA[0] = *(const ulonglong2*)&sE [oA];
                inA[1] = *(const ulonglong2*)&sO [oA];
                inA[2] = *(const ulonglong2*)&sE2[oA];
                inB[0] = *(const ulonglong2*)&sE [oB];
                inB[1] = *(const ulonglong2*)&sO [oB];
                inB[2] = *(const ulonglong2*)&sE2[oB];
                #pragma unroll
                for (int kw = 0; kw < 3; kw++) {
                    const float* wp = &sW[(ci * 9 + kh * 3 + kw) * 128 + tc * 16];
                    ulonglong2 wA = *(const ulonglong2*)(wp);
                    ulonglong2 wB = *(const ulonglong2*)(wp + 4);
                    ulonglong2 wC = *(const ulonglong2*)(wp + 8);
                    ulonglong2 wD = *(const ulonglong2*)(wp + 12);
                    ffma2(acc[0][0][0], inA[kw].x, wA.x); ffma2(acc[0][0][1], inA[kw].x, wA.y);
                    ffma2(acc[0][0][2], inA[kw].x, wB.x); ffma2(acc[0][0][3], inA[kw].x, wB.y);
                    ffma2(acc[0][0][4], inA[kw].x, wC.x); ffma2(acc[0][0][5], inA[kw].x, wC.y);
                    ffma2(acc[0][0][6], inA[kw].x, wD.x); ffma2(acc[0][0][7], inA[kw].x, wD.y);
                    ffma2(acc[0][1][0], inA[kw].y, wA.x); ffma2(acc[0][1][1], inA[kw].y, wA.y);
                    ffma2(acc[0][1][2], inA[kw].y, wB.x); ffma2(acc[0][1][3], inA[kw].y, wB.y);
                    ffma2(acc[0][1][4], inA[kw].y, wC.x); ffma2(acc[0][1][5], inA[kw].y, wC.y);
                    ffma2(acc[0][1][6], inA[kw].y, wD.x); ffma2(acc[0][1][7], inA[kw].y, wD.y);
                    ffma2(acc[1][0][0], inB[kw].x, wA.x); ffma2(acc[1][0][1], inB[kw].x, wA.y);
                    ffma2(acc[1][0][2], inB[kw].x, wB.x); ffma2(acc[1][0][3], inB[kw].x, wB.y);
                    ffma2(acc[1][0][4], inB[kw].x, wC.x); ffma2(acc[1][0][5], inB[kw].x, wC.y);
                    ffma2(acc[1][0][6], inB[kw].x, wD.x); ffma2(acc[1][0][7], inB[kw].x, wD.y);
                    ffma2(acc[1][1][0], inB[kw].y, wA.x); ffma2(acc[1][1][1], inB[kw].y, wA.y);
                    ffma2(acc[1][1][2], inB[kw].y, wB.x); ffma2(acc[1][1][3], inB[kw].y, wB.y);
                    ffma2(acc[1][1][4], inB[kw].y, wC.x); ffma2(acc[1][1][5], inB[kw].y, wC.y);
                    ffma2(acc[1][1][6], inB[kw].y, wD.x); ffma2(acc[1][1][7], inB[kw].y, wD.y);
                }
            }
        }
        __syncthreads();
    }

    // epilogue: bias + channel shuffle, float4 stores
    #pragma unroll
    for (int j = 0; j < 8; j++) {
        int co = tc * 8 + j;
        float bias = sq_b[co];
        int oc = ((co & 15) << 3) + (co >> 4);
        #pragma unroll
        for (int yy = 0; yy < 2; yy++) {
            int y = y0 + 2 * ty + yy;
            float4 o;
            unpack2(acc[yy][0][j], o.x, o.y);
            unpack2(acc[yy][1][j], o.z, o.w);
            o.x += bias; o.y += bias; o.z += bias; o.w += bias;
            *(float4*)&out[((size_t)(n * 128 + oc) * HO + y) * WO + x0 + 4 * tx] = o;
        }
    }
}

// ---------------- 5) vertical CondConv (3x1, s2) — single-shot cp.async ----------------
// smem: s_in[32*9*32]=9216 floats, s_w[32*3*64]=6144 floats -> 61440 B
#define V_SMEM_BYTES ((32*9*32 + 32*3*64) * 4)
__global__ void __launch_bounds__(256)
v_kernel(const float* __restrict__ x) {
    extern __shared__ float sm[];
    float* s_in = sm;
    float* s_w  = sm + 32*9*32;
    const int tid = threadIdx.x;
    const int tx = tid & 15, ty = (tid >> 4) & 3, tc = tid >> 6;
    const int lane = tid & 31, wid = tid >> 5;
    const int x0 = blockIdx.x * 32, y0 = blockIdx.y * 4, n = blockIdx.z;
    const int gy0 = 2*y0 - 1;
    const uint sbase = smem_u32(sm);

    // load everything: 288 rows (32 ci x 9), 32 even cols each
    for (int row = wid; row < 288; row += 8) {
        int ci = row / 9, r = row - ci * 9;
        int gy = gy0 + r;
        const float* src = x + ((size_t)(n * C_IN + ci) * HI + gy) * WI + 2 * x0;
        bool ok = (gy >= 0);
        uint ro = sbase + (uint)row * 32 * 4;
        cp4(ro + lane * 4, ok ? src + 2 * lane : x, ok ? 4u : 0u);
    }
    {
        const float4* wsrc = (const float4*)(g_wv + (size_t)n * 32 * 192);
        uint wb = sbase + 32*9*32 * 4;
        #pragma unroll
        for (int i = 0; i < 6; i++) cp16(wb + (tid + i * 256) * 16, wsrc + tid + i * 256);
    }
    CP_COMMIT(); CP_WAIT(0);
    __syncthreads();

    ull acc[8];
    #pragma unroll
    for (int j = 0; j < 8; j++) acc[j] = 0ULL;

    #pragma unroll 8
    for (int ci = 0; ci < 32; ci++) {
        #pragma unroll
        for (int kh = 0; kh < 3; kh++) {
            int r = 2 * ty + kh;
            ull in2 = *(const ull*)&s_in[(ci * 9 + r) * 32 + 2 * tx];
            const float* wp = &s_w[(ci * 3 + kh) * 64 + tc * 16];
            ulonglong2 wA = *(const ulonglong2*)(wp);
            ulonglong2 wB = *(const ulonglong2*)(wp + 4);
            ulonglong2 wC = *(const ulonglong2*)(wp + 8);
            ulonglong2 wD = *(const ulonglong2*)(wp + 12);
            ffma2(acc[0], in2, wA.x); ffma2(acc[1], in2, wA.y);
            ffma2(acc[2], in2, wB.x); ffma2(acc[3], in2, wB.y);
            ffma2(acc[4], in2, wC.x); ffma2(acc[5], in2, wC.y);
            ffma2(acc[6], in2, wD.x); ffma2(acc[7], in2, wD.y);
        }
    }
    int y = y0 + ty;
    #pragma unroll
    for (int j = 0; j < 8; j++) {
        int co = tc * 8 + j;
        float lo, hi; unpack2(acc[j], lo, hi);
        *(float2*)&g_vraw[((size_t)(n * 32 + co) * HO + y) * WO + x0 + 2 * tx] =
            make_float2(lo, hi);
    }
}

// ---------------- 6) horizontal CondConv (1x3, s2) — single-shot cp.async ----------------
// smem: sE/sO/sE2 [32*4*34]=4352 each, s_w 6144 -> 19200 floats = 76800 B
#define H_E   0
#define H_O   4352
#define H_E2  8704
#define H_W   13056
#define H_SMEM_BYTES ((3*4352 + 6144) * 4)
__global__ void __launch_bounds__(256)
h_kernel(const float* __restrict__ x) {
    extern __shared__ float sm[];
    const int tid = threadIdx.x;
    const int tx = tid & 15, ty = (tid >> 4) & 3, tc = tid >> 6;
    const int lane = tid & 31, wid = tid >> 5;
    const int x0 = blockIdx.x * 32, y0 = blockIdx.y * 4, n = blockIdx.z;
    const int gx0 = 2*x0 - 1;
    const uint sbase = smem_u32(sm);

    // load: 128 rows (32 ci x 4 even rows), 65 cols deinterleaved
    for (int row = wid; row < 128; row += 8) {
        int ci = row >> 2, r = row & 3;
        int gy = 2 * (y0 + r);
        const float* src = x + ((size_t)(n * C_IN + C_H + ci) * HI + gy) * WI + gx0;
        uint ro = sbase + (uint)row * 34 * 4;
        for (int c = lane; c < 65; c += 32) {
            int gx = gx0 + c;
            bool ok = (gx >= 0);
            uint sz = ok ? 4u : 0u;
            const float* s = ok ? src + c : x;
            int h = c >> 1;
            if (c & 1) {
                cp4(ro + H_O * 4 + h * 4, s, sz);
            } else {
                cp4(ro + H_E * 4 + h * 4, s, sz);
                if (h) cp4(ro + H_E2 * 4 + (h - 1) * 4, s, sz);
            }
        }
    }
    {
        const float4* wsrc = (const float4*)(g_wh + (size_t)n * 32 * 192);
        uint wb = sbase + H_W * 4;
        #pragma unroll
        for (int i = 0; i < 6; i++) cp16(wb + (tid + i * 256) * 16, wsrc + tid + i * 256);
    }
    CP_COMMIT(); CP_WAIT(0);
    __syncthreads();

    const float* sE  = sm + H_E;
    const float* sO  = sm + H_O;
    const float* sE2 = sm + H_E2;
    const float* s_w = sm + H_W;

    ull acc[8];
    #pragma unroll
    for (int j = 0; j < 8; j++) acc[j] = 0ULL;

    #pragma unroll 8
    for (int ci = 0; ci < 32; ci++) {
        const int o = (ci * 4 + ty) * 34 + 2 * tx;
        ull p[3] = { *(const ull*)&sE[o], *(const ull*)&sO[o], *(const ull*)&sE2[o] };
        #pragma unroll
        for (int kw = 0; kw < 3; kw++) {
            const float* wp = &s_w[(ci * 3 + kw) * 64 + tc * 16];
            ulonglong2 wA = *(const ulonglong2*)(wp);
            ulonglong2 wB = *(const ulonglong2*)(wp + 4);
            ulonglong2 wC = *(const ulonglong2*)(wp + 8);
            ulonglong2 wD = *(const ulonglong2*)(wp + 12);
            ffma2(acc[0], p[kw], wA.x); ffma2(acc[1], p[kw], wA.y);
            ffma2(acc[2], p[kw], wB.x); ffma2(acc[3], p[kw], wB.y);
            ffma2(acc[4], p[kw], wC.x); ffma2(acc[5], p[kw], wC.y);
            ffma2(acc[6], p[kw], wD.x); ffma2(acc[7], p[kw], wD.y);
        }
    }
    int y = y0 + ty;
    #pragma unroll
    for (int j = 0; j < 8; j++) {
        int co = tc * 8 + j;
        float lo, hi; unpack2(acc[j], lo, hi);
        *(float2*)&g_hraw[((size_t)(n * 32 + co) * HO + y) * WO + x0 + 2 * tx] =
            make_float2(lo, hi);
    }
}

// ---------------- 7) BN statistics ----------------
__global__ void stats_kernel() {
    int bid = blockIdx.x;
    int dir = bid >> 7, c = (bid >> 2) & 31, sl = bid & 3;
    const float* base = dir ? g_hraw : g_vraw;
    float s = 0.f, q = 0.f;
    for (int i = threadIdx.x; i < 18432; i += 256) {
        int e4 = sl * 18432 + i;
        int n = e4 / 9216, ri = e4 % 9216;
        float4 v = ((const float4*)(base + (size_t)(n * 32 + c) * HWO))[ri];
        s += v.x + v.y + v.z + v.w;
        q += v.x * v.x + v.y * v.y + v.z * v.z + v.w * v.w;
    }
    __shared__ float red[512];
    red[threadIdx.x] = s; red[256 + threadIdx.x] = q;
    __syncthreads();
    for (int o = 128; o > 0; o >>= 1) {
        if (threadIdx.x < o) {
            red[threadIdx.x] += red[threadIdx.x + o];
            red[256 + threadIdx.x] += red[256 + threadIdx.x + o];
        }
        __syncthreads();
    }
    if (threadIdx.x == 0) {
        atomicAdd(&g_stats[(dir * 32 + c) * 2],     red[0]);
        atomicAdd(&g_stats[(dir * 32 + c) * 2 + 1], red[256]);
    }
}

// ---------------- 8) BN apply + shuffle ----------------
__global__ void bn_kernel(const float* __restrict__ gv, const float* __restrict__ bv,
                          const float* __restrict__ gh, const float* __restrict__ bh,
                          float* __restrict__ out) {
    int bid = blockIdx.x;
    int dir = bid >> 8, co = (bid >> 3) & 31, n = bid & 7;
    float sum = g_stats[(dir * 32 + co) * 2];
    float sq  = g_stats[(dir * 32 + co) * 2 + 1];
    const float inv = 1.f / (float)NPIX_CH;
    float m = sum * inv;
    float var = sq * inv - m * m;
    float gam = (dir ? gh : gv)[co];
    float bet = (dir ? bh : bv)[co];
    float scale = gam * rsqrtf(var + 1e-5f);
    float shift = bet - m * scale;
    int oc = ((co & 15) << 3) + 4 + 2 * dir + (co >> 4);
    const float4* src = (const float4*)((dir ? g_hraw : g_vraw) + (size_t)(n * 32 + co) * HWO);
    float4* dst = (float4*)(out + (size_t)(n * 128 + oc) * HWO);
    for (int i = threadIdx.x; i < 9216; i += 256) {
        float4 v = src[i];
        v.x = v.x * scale + shift; v.y = v.y * scale + shift;
        v.z = v.z * scale + shift; v.w = v.w * scale + shift;
        dst[i] = v;
    }
}

// ---------------- launch ----------------
extern "C" void kernel_launch(void* const* d_in, const int* in_sizes, int n_in,
                              void* d_out, int out_size) {
    const float* x      = (const float*)d_in[0];
    const float* sq_w   = (const float*)d_in[1];
    const float* sq_b   = (const float*)d_in[2];
    const float* aw_v   = (const float*)d_in[3];
    const float* ab_v   = (const float*)d_in[4];
    const float* w_v    = (const float*)d_in[5];
    const float* bn_v_g = (const float*)d_in[6];
    const float* bn_v_b = (const float*)d_in[7];
    const float* aw_h   = (const float*)d_in[8];
    const float* ab_h   = (const float*)d_in[9];
    const float* w_h    = (const float*)d_in[10];
    const float* bn_h_g = (const float*)d_in[11];
    const float* bn_h_b = (const float*)d_in[12];
    float* out = (float*)d_out;

    cudaFuncSetAttribute(sq_kernel, cudaFuncAttributeMaxDynamicSharedMemorySize, SQ_SMEM_BYTES);
    cudaFuncSetAttribute(v_kernel,  cudaFuncAttributeMaxDynamicSharedMemorySize, V_SMEM_BYTES);
    cudaFuncSetAttribute(h_kernel,  cudaFuncAttributeMaxDynamicSharedMemorySize, H_SMEM_BYTES);

    mean_kernel<<<N_B * C_IN, 256>>>(x);
    att_kernel<<<1, 128>>>(aw_v, ab_v, aw_h, ab_h);
    prep_kernel<<<336, 256>>>(sq_w, w_v, w_h);
    sq_kernel<<<dim3(WO/64, HO/4, N_B), 256, SQ_SMEM_BYTES>>>(x, sq_b, out);
    v_kernel<<<dim3(WO/32, HO/4, N_B), 256, V_SMEM_BYTES>>>(x);
    h_kernel<<<dim3(WO/32, HO/4, N_B), 256, H_SMEM_BYTES>>>(x);
    stats_kernel<<<256, 256>>>();
    bn_kernel<<<512, 256>>>(bn_v_g, bn_v_b, bn_h_g, bn_h_b, out);
}

// round 7
// speedup vs baseline: 1.7246x; 1.1220x over previous
#include <cuda_runtime.h>
#include <math.h>

typedef unsigned long long ull;
typedef unsigned int uint;

#define N_B 8
#define C_IN 64
#define C_H 32
#define HI 384
#define WI 384
#define HO 192
#define WO 192
#define HWI (HI*WI)
#define HWO (HO*WO)
#define NPIX_CH (N_B*HWO)

// ---------------- scratch ----------------
__device__ float g_mean[N_B*C_IN];                       // channel SUMS (scaled in att)
__device__ float g_att[2*N_B*4];
__device__ float g_sqw[C_IN*9*128];                      // [ci][k9][co*2 dup]
__device__ float g_wv[N_B*C_H*3*64];
__device__ float g_wh[N_B*C_H*3*64];
__device__ float g_ev [(size_t)N_B*C_IN*HI*192];         // Ev[k]  = x[2k]
__device__ float g_od [(size_t)N_B*C_IN*HI*192];         // Od[k]  = x[2k+1]
__device__ float g_ods[(size_t)N_B*C_IN*HI*192];         // OdS[k] = x[2k-1], OdS[0]=0
__device__ float g_vraw[(size_t)N_B*C_H*HWO];
__device__ float g_hraw[(size_t)N_B*C_H*HWO];
__device__ float g_stats[2*C_H*2];

// ---------------- helpers ----------------
__device__ __forceinline__ void unpack2(ull v, float& a, float& b) {
    asm("mov.b64 {%0, %1}, %2;" : "=f"(a), "=f"(b) : "l"(v));
}
__device__ __forceinline__ void ffma2(ull& d, ull a, ull b) {
    asm("fma.rn.f32x2 %0, %1, %2, %0;" : "+l"(d) : "l"(a), "l"(b));
}
__device__ __forceinline__ uint smem_u32(const void* p) {
    uint a; asm("{ .reg .u64 t; cvta.to.shared.u64 t, %1; cvt.u32.u64 %0, t; }" : "=r"(a) : "l"(p));
    return a;
}
__device__ __forceinline__ void cp16(uint dst, const void* src) {
    asm volatile("{ .reg .u64 g; cvta.to.global.u64 g, %1;"
                 " cp.async.cg.shared.global [%0], [g], 16; }"
                 :: "r"(dst), "l"(src) : "memory");
}
__device__ __forceinline__ void cp16z(uint dst, const void* src, uint sz) {
    asm volatile("{ .reg .u64 g; cvta.to.global.u64 g, %1;"
                 " cp.async.cg.shared.global [%0], [g], 16, %2; }"
                 :: "r"(dst), "l"(src), "r"(sz) : "memory");
}
#define CP_COMMIT() asm volatile("cp.async.commit_group;" ::: "memory")
#define CP_WAIT(n)  asm volatile("cp.async.wait_group %0;" :: "n"(n) : "memory")

// ---------------- 1) global deinterleave + channel sums ----------------
// One block per (n,c) channel. Writes Ev/Od/OdS rows (pitch 192) + channel sum.
__global__ void __launch_bounds__(256)
deint_kernel(const float* __restrict__ x) {
    int nc = blockIdx.x;
    const float* src = x + (size_t)nc * HWI;
    float* ev  = g_ev  + (size_t)nc * HI * 192;
    float* od  = g_od  + (size_t)nc * HI * 192;
    float* ods = g_ods + (size_t)nc * HI * 192;
    const int lane = threadIdx.x & 31, wid = threadIdx.x >> 5;
    float s = 0.f;

    for (int row = wid; row < HI; row += 8) {            // warp per row
        const float* r = src + (size_t)row * WI;
        float* evr  = ev  + row * 192;
        float* odr  = od  + row * 192;
        float* odsr = ods + row * 192;
        float carry = 0.f;                               // broadcast x[32*8*it - 1]
        #pragma unroll
        for (int it = 0; it < 2; it++) {
            int g = it * 32 + lane;                      // 8-float group
            bool act = g < 48;
            float4 a = act ? *(const float4*)(r + 8 * g)     : make_float4(0,0,0,0);
            float4 b = act ? *(const float4*)(r + 8 * g + 4) : make_float4(0,0,0,0);
            float myhi = b.w;                            // x[8g+7]
            float prev = __shfl_up_sync(0xffffffffu, myhi, 1);   // uniform
            if (lane == 0) prev = carry;                 // register read, no shuffle
            if (act) {
                *(float4*)(evr  + 4*g) = make_float4(a.x, a.z, b.x, b.z);
                *(float4*)(odr  + 4*g) = make_float4(a.y, a.w, b.y, b.w);
                *(float4*)(odsr + 4*g) = make_float4(prev, a.y, a.w, b.y);
                s += a.x + a.y + a.z + a.w + b.x + b.y + b.z + b.w;
            }
            carry = __shfl_sync(0xffffffffu, myhi, 31);  // uniform broadcast
        }
    }
    __shared__ float red[256];
    red[threadIdx.x] = s; __syncthreads();
    for (int o = 128; o > 0; o >>= 1) {
        if (threadIdx.x < o) red[threadIdx.x] += red[threadIdx.x + o];
        __syncthreads();
    }
    if (threadIdx.x == 0) g_mean[nc] = red[0];
}

// ---------------- 2) attention + zero stats ----------------
__global__ void att_kernel(const float* __restrict__ aw_v, const float* __restrict__ ab_v,
                           const float* __restrict__ aw_h, const float* __restrict__ ab_h) {
    int t = threadIdx.x;
    if (t < 64) {
        int dir = t >> 5, n = (t >> 2) & 7, k = t & 3;
        const float* aw = dir ? aw_h : aw_v;
        const float* ab = dir ? ab_h : ab_v;
        const float* m = g_mean + n * C_IN + dir * C_H;
        float s = 0.f;
        #pragma unroll
        for (int ci = 0; ci < C_H; ci++) s += m[ci] * aw[k * C_H + ci];
        s = s * (1.f / (float)HWI) + ab[k];
        g_att[t] = 1.f / (1.f + expf(-s));
    }
    if (t < 128) g_stats[t] = 0.f;
}

// ---------------- 3) weight prep ----------------
__global__ void prep_kernel(const float* __restrict__ sq_w,
                            const float* __restrict__ w_v, const float* __restrict__ w_h) {
    int idx = blockIdx.x * 256 + threadIdx.x;
    if (idx < C_IN*9*64) {
        int co = idx & 63, k = (idx >> 6) % 9, ci = idx / 576;
        float w = sq_w[(co * C_IN + ci) * 9 + k];
        int o = (ci * 9 + k) * 128 + co * 2;
        g_sqw[o] = w; g_sqw[o + 1] = w;
    } else if (idx < C_IN*9*64 + 2*24576) {
        int r = idx - C_IN*9*64;
        int dir = r / 24576; r %= 24576;
        int co = r & 31, kh = (r >> 5) % 3, ci = (r / 96) & 31, n = r / 3072;
        const float* w = dir ? w_h : w_v;
        const float* att = &g_att[dir * 32 + n * 4];
        float v = 0.f;
        #pragma unroll
        for (int k = 0; k < 4; k++) v += att[k] * w[((k * 32 + co) * 32 + ci) * 3 + kh];
        float* dst = dir ? g_wh : g_wv;
        int o = ((n * 32 + ci) * 3 + kh) * 64 + co * 2;
        dst[o] = v; dst[o + 1] = v;
    }
}

// ---------------- 4) square 3x3 s2 conv — vectorized cp.async double-buffered ----------------
// Block: 64 out-x * 4 out-y * 64 co. Thread (tx16, ty2, tc8).
// Stage (floats): A1(OdS)[36*64] A2(Ev)[36*64] A3(Od)[36*64] W[4*9*128]
#define SQ_ARR   2304          // 36*64
#define SQ_W_OFF 6912          // 3*2304
#define SQ_ST    11520         // + 4608 weights
#define SQ_SMEM_BYTES (2*SQ_ST*4)

__global__ void __launch_bounds__(256, 2)
sq_kernel(const float* __restrict__ x, const float* __restrict__ sq_b, float* __restrict__ out) {
    extern __shared__ float sm[];
    const int tid = threadIdx.x;
    const int tx = tid & 15, ty = (tid >> 4) & 1, tc = tid >> 5;
    const int lane = tid & 31, wid = tid >> 5;
    const int x0 = blockIdx.x * 64, y0 = blockIdx.y * 4, n = blockIdx.z;
    const int gy0 = 2*y0 - 1;
    const uint sbase = smem_u32(sm);

    ull acc[2][2][8];
    #pragma unroll
    for (int a = 0; a < 2; a++)
        #pragma unroll
        for (int b = 0; b < 2; b++)
            #pragma unroll
            for (int j = 0; j < 8; j++) acc[a][b][j] = 0ULL;

    auto load_chunk = [&](int ci0, int stage) {
        uint st = sbase + (uint)stage * (SQ_ST * 4);
        for (int row = wid; row < 36; row += 8) {
            int ci = row / 9, r = row - ci * 9;
            int gy = gy0 + r;
            bool vy = (gy >= 0);
            size_t rb = ((size_t)(n * C_IN + ci0 + ci) * HI + (vy ? gy : 0)) * 192 + x0;
            uint so = st + (uint)row * 64 * 4;
            uint sz = vy ? 16u : 0u;
            #pragma unroll
            for (int i = lane; i < 48; i += 32) {
                int arr = i >> 4, g = i & 15;
                const float* gs = (arr == 0 ? g_ods : arr == 1 ? g_ev : g_od) + rb + g * 4;
                cp16z(so + (uint)arr * (SQ_ARR * 4) + g * 16, gs, sz);
            }
        }
        const float4* wsrc = (const float4*)(g_sqw + ci0 * 9 * 128);
        uint wb = st + SQ_W_OFF * 4;
        #pragma unroll
        for (int i = 0; i < 5; i++) {
            int k = tid + i * 256;
            if (k < 1152) cp16(wb + k * 16, wsrc + k);
        }
    };

    load_chunk(0, 0);
    CP_COMMIT();

    for (int ch = 0; ch < 16; ch++) {
        if (ch < 15) {
            load_chunk((ch + 1) * 4, (ch + 1) & 1);
            CP_COMMIT();
            CP_WAIT(1);
        } else {
            CP_WAIT(0);
        }
        __syncthreads();

        const float* base = sm + (ch & 1) * SQ_ST;
        const float* sW   = base + SQ_W_OFF;

        #pragma unroll
        for (int ci = 0; ci < 4; ci++) {
            #pragma unroll
            for (int kh = 0; kh < 3; kh++) {
                const int oA = ((ci * 9 + 4 * ty + kh)) * 64 + 4 * tx;
                const int oB = oA + 2 * 64;
                ulonglong2 inA[3], inB[3];
                inA[0] = *(const ulonglong2*)&base[0*SQ_ARR + oA];   // kw0 (OdS)
                inA[1] = *(const ulonglong2*)&base[1*SQ_ARR + oA];   // kw1 (Ev)
                inA[2] = *(const ulonglong2*)&base[2*SQ_ARR + oA];   // kw2 (Od)
                inB[0] = *(const ulonglong2*)&base[0*SQ_ARR + oB];
                inB[1] = *(const ulonglong2*)&base[1*SQ_ARR + oB];
                inB[2] = *(const ulonglong2*)&base[2*SQ_ARR + oB];
                #pragma unroll
                for (int kw = 0; kw < 3; kw++) {
                    const float* wp = &sW[(ci * 9 + kh * 3 + kw) * 128 + tc * 16];
                    ulonglong2 wA = *(const ulonglong2*)(wp);
                    ulonglong2 wB = *(const ulonglong2*)(wp + 4);
                    ulonglong2 wC = *(const ulonglong2*)(wp + 8);
                    ulonglong2 wD = *(const ulonglong2*)(wp + 12);
                    ffma2(acc[0][0][0], inA[kw].x, wA.x); ffma2(acc[0][0][1], inA[kw].x, wA.y);
                    ffma2(acc[0][0][2], inA[kw].x, wB.x); ffma2(acc[0][0][3], inA[kw].x, wB.y);
                    ffma2(acc[0][0][4], inA[kw].x, wC.x); ffma2(acc[0][0][5], inA[kw].x, wC.y);
                    ffma2(acc[0][0][6], inA[kw].x, wD.x); ffma2(acc[0][0][7], inA[kw].x, wD.y);
                    ffma2(acc[0][1][0], inA[kw].y, wA.x); ffma2(acc[0][1][1], inA[kw].y, wA.y);
                    ffma2(acc[0][1][2], inA[kw].y, wB.x); ffma2(acc[0][1][3], inA[kw].y, wB.y);
                    ffma2(acc[0][1][4], inA[kw].y, wC.x); ffma2(acc[0][1][5], inA[kw].y, wC.y);
                    ffma2(acc[0][1][6], inA[kw].y, wD.x); ffma2(acc[0][1][7], inA[kw].y, wD.y);
                    ffma2(acc[1][0][0], inB[kw].x, wA.x); ffma2(acc[1][0][1], inB[kw].x, wA.y);
                    ffma2(acc[1][0][2], inB[kw].x, wB.x); ffma2(acc[1][0][3], inB[kw].x, wB.y);
                    ffma2(acc[1][0][4], inB[kw].x, wC.x); ffma2(acc[1][0][5], inB[kw].x, wC.y);
                    ffma2(acc[1][0][6], inB[kw].x, wD.x); ffma2(acc[1][0][7], inB[kw].x, wD.y);
                    ffma2(acc[1][1][0], inB[kw].y, wA.x); ffma2(acc[1][1][1], inB[kw].y, wA.y);
                    ffma2(acc[1][1][2], inB[kw].y, wB.x); ffma2(acc[1][1][3], inB[kw].y, wB.y);
                    ffma2(acc[1][1][4], inB[kw].y, wC.x); ffma2(acc[1][1][5], inB[kw].y, wC.y);
                    ffma2(acc[1][1][6], inB[kw].y, wD.x); ffma2(acc[1][1][7], inB[kw].y, wD.y);
                }
            }
        }
        __syncthreads();
    }

    #pragma unroll
    for (int j = 0; j < 8; j++) {
        int co = tc * 8 + j;
        float bias = sq_b[co];
        int oc = ((co & 15) << 3) + (co >> 4);
        #pragma unroll
        for (int yy = 0; yy < 2; yy++) {
            int y = y0 + 2 * ty + yy;
            float4 o;
            unpack2(acc[yy][0][j], o.x, o.y);
            unpack2(acc[yy][1][j], o.z, o.w);
            o.x += bias; o.y += bias; o.z += bias; o.w += bias;
            *(float4*)&out[((size_t)(n * 128 + oc) * HO + y) * WO + x0 + 4 * tx] = o;
        }
    }
}

// ---------------- 5) vertical CondConv (3x1, s2) ----------------
#define V_SMEM_BYTES ((288*32 + 32*3*64) * 4)
__global__ void __launch_bounds__(256)
v_kernel(const float* __restrict__ x) {
    extern __shared__ float sm[];
    float* s_in = sm;
    float* s_w  = sm + 288*32;
    const int tid = threadIdx.x;
    const int tx = tid & 15, ty = (tid >> 4) & 3, tc = tid >> 6;
    const int x0 = blockIdx.x * 32, y0 = blockIdx.y * 4, n = blockIdx.z;
    const int gy0 = 2*y0 - 1;
    const uint sbase = smem_u32(sm);

    for (int i = tid; i < 2304; i += 256) {          // 288 rows x 8 cp16
        int row = i >> 3, g = i & 7;
        int ci = row / 9, r = row - ci * 9;
        int gy = gy0 + r;
        bool vy = (gy >= 0);
        const float* gs = g_ev + ((size_t)(n * C_IN + ci) * HI + (vy ? gy : 0)) * 192 + x0 + g * 4;
        cp16z(sbase + (uint)i * 16, gs, vy ? 16u : 0u);
    }
    {
        const float4* wsrc = (const float4*)(g_wv + (size_t)n * 32 * 192);
        uint wb = sbase + 288*32 * 4;
        #pragma unroll
        for (int i = 0; i < 6; i++) cp16(wb + (tid + i * 256) * 16, wsrc + tid + i * 256);
    }
    CP_COMMIT(); CP_WAIT(0);
    __syncthreads();

    ull acc[8];
    #pragma unroll
    for (int j = 0; j < 8; j++) acc[j] = 0ULL;

    #pragma unroll 8
    for (int ci = 0; ci < 32; ci++) {
        #pragma unroll
        for (int kh = 0; kh < 3; kh++) {
            int r = 2 * ty + kh;
            ull in2 = *(const ull*)&s_in[(ci * 9 + r) * 32 + 2 * tx];
            const float* wp = &s_w[(ci * 3 + kh) * 64 + tc * 16];
            ulonglong2 wA = *(const ulonglong2*)(wp);
            ulonglong2 wB = *(const ulonglong2*)(wp + 4);
            ulonglong2 wC = *(const ulonglong2*)(wp + 8);
            ulonglong2 wD = *(const ulonglong2*)(wp + 12);
            ffma2(acc[0], in2, wA.x); ffma2(acc[1], in2, wA.y);
            ffma2(acc[2], in2, wB.x); ffma2(acc[3], in2, wB.y);
            ffma2(acc[4], in2, wC.x); ffma2(acc[5], in2, wC.y);
            ffma2(acc[6], in2, wD.x); ffma2(acc[7], in2, wD.y);
        }
    }
    int y = y0 + ty;
    #pragma unroll
    for (int j = 0; j < 8; j++) {
        int co = tc * 8 + j;
        float lo, hi; unpack2(acc[j], lo, hi);
        *(float2*)&g_vraw[((size_t)(n * 32 + co) * HO + y) * WO + x0 + 2 * tx] =
            make_float2(lo, hi);
    }
}

// ---------------- 6) horizontal CondConv (1x3, s2) ----------------
// arrays: A1(OdS) A2(Ev) A3(Od), 128 rows x 32 floats each
#define H_ARR  4096
#define H_W_OFF 12288
#define H_SMEM_BYTES ((3*4096 + 6144) * 4)
__global__ void __launch_bounds__(256)
h_kernel(const float* __restrict__ x) {
    extern __shared__ float sm[];
    const int tid = threadIdx.x;
    const int tx = tid & 15, ty = (tid >> 4) & 3, tc = tid >> 6;
    const int x0 = blockIdx.x * 32, y0 = blockIdx.y * 4, n = blockIdx.z;
    const uint sbase = smem_u32(sm);

    for (int i = tid; i < 3072; i += 256) {          // 3 arrays x 128 rows x 8 cp16
        int arr = i >> 10, j = i & 1023;
        int row = j >> 3, g = j & 7;
        int ci = row >> 2, r = row & 3;
        int gy = 2 * (y0 + r);
        const float* src = (arr == 0 ? g_ods : arr == 1 ? g_ev : g_od)
                           + ((size_t)(n * C_IN + C_H + ci) * HI + gy) * 192 + x0 + g * 4;
        cp16(sbase + (uint)i * 16, src);
    }
    {
        const float4* wsrc = (const float4*)(g_wh + (size_t)n * 32 * 192);
        uint wb = sbase + H_W_OFF * 4;
        #pragma unroll
        for (int i = 0; i < 6; i++) cp16(wb + (tid + i * 256) * 16, wsrc + tid + i * 256);
    }
    CP_COMMIT(); CP_WAIT(0);
    __syncthreads();

    const float* s_w = sm + H_W_OFF;

    ull acc[8];
    #pragma unroll
    for (int j = 0; j < 8; j++) acc[j] = 0ULL;

    #pragma unroll 8
    for (int ci = 0; ci < 32; ci++) {
        const int o = (ci * 4 + ty) * 32 + 2 * tx;
        ull p[3] = { *(const ull*)&sm[0*H_ARR + o],      // kw0 (OdS)
                     *(const ull*)&sm[1*H_ARR + o],      // kw1 (Ev)
                     *(const ull*)&sm[2*H_ARR + o] };    // kw2 (Od)
        #pragma unroll
        for (int kw = 0; kw < 3; kw++) {
            const float* wp = &s_w[(ci * 3 + kw) * 64 + tc * 16];
            ulonglong2 wA = *(const ulonglong2*)(wp);
            ulonglong2 wB = *(const ulonglong2*)(wp + 4);
            ulonglong2 wC = *(const ulonglong2*)(wp + 8);
            ulonglong2 wD = *(const ulonglong2*)(wp + 12);
            ffma2(acc[0], p[kw], wA.x); ffma2(acc[1], p[kw], wA.y);
            ffma2(acc[2], p[kw], wB.x); ffma2(acc[3], p[kw], wB.y);
            ffma2(acc[4], p[kw], wC.x); ffma2(acc[5], p[kw], wC.y);
            ffma2(acc[6], p[kw], wD.x); ffma2(acc[7], p[kw], wD.y);
        }
    }
    int y = y0 + ty;
    #pragma unroll
    for (int j = 0; j < 8; j++) {
        int co = tc * 8 + j;
        float lo, hi; unpack2(acc[j], lo, hi);
        *(float2*)&g_hraw[((size_t)(n * 32 + co) * HO + y) * WO + x0 + 2 * tx] =
            make_float2(lo, hi);
    }
}

// ---------------- 7) BN statistics ----------------
__global__ void stats_kernel() {
    int bid = blockIdx.x;
    int dir = bid >> 7, c = (bid >> 2) & 31, sl = bid & 3;
    const float* base = dir ? g_hraw : g_vraw;
    float s = 0.f, q = 0.f;
    for (int i = threadIdx.x; i < 18432; i += 256) {
        int e4 = sl * 18432 + i;
        int n = e4 / 9216, ri = e4 % 9216;
        float4 v = ((const float4*)(base + (size_t)(n * 32 + c) * HWO))[ri];
        s += v.x + v.y + v.z + v.w;
        q += v.x * v.x + v.y * v.y + v.z * v.z + v.w * v.w;
    }
    __shared__ float red[512];
    red[threadIdx.x] = s; red[256 + threadIdx.x] = q;
    __syncthreads();
    for (int o = 128; o > 0; o >>= 1) {
        if (threadIdx.x < o) {
            red[threadIdx.x] += red[threadIdx.x + o];
            red[256 + threadIdx.x] += red[256 + threadIdx.x + o];
        }
        __syncthreads();
    }
    if (threadIdx.x == 0) {
        atomicAdd(&g_stats[(dir * 32 + c) * 2],     red[0]);
        atomicAdd(&g_stats[(dir * 32 + c) * 2 + 1], red[256]);
    }
}

// ---------------- 8) BN apply + shuffle ----------------
__global__ void bn_kernel(const float* __restrict__ gv, const float* __restrict__ bv,
                          const float* __restrict__ gh, const float* __restrict__ bh,
                          float* __restrict__ out) {
    int bid = blockIdx.x;
    int dir = bid >> 8, co = (bid >> 3) & 31, n = bid & 7;
    float sum = g_stats[(dir * 32 + co) * 2];
    float sq  = g_stats[(dir * 32 + co) * 2 + 1];
    const float inv = 1.f / (float)NPIX_CH;
    float m = sum * inv;
    float var = sq * inv - m * m;
    float gam = (dir ? gh : gv)[co];
    float bet = (dir ? bh : bv)[co];
    float scale = gam * rsqrtf(var + 1e-5f);
    float shift = bet - m * scale;
    int oc = ((co & 15) << 3) + 4 + 2 * dir + (co >> 4);
    const float4* src = (const float4*)((dir ? g_hraw : g_vraw) + (size_t)(n * 32 + co) * HWO);
    float4* dst = (float4*)(out + (size_t)(n * 128 + oc) * HWO);
    for (int i = threadIdx.x; i < 9216; i += 256) {
        float4 v = src[i];
        v.x = v.x * scale + shift; v.y = v.y * scale + shift;
        v.z = v.z * scale + shift; v.w = v.w * scale + shift;
        dst[i] = v;
    }
}

// ---------------- launch ----------------
extern "C" void kernel_launch(void* const* d_in, const int* in_sizes, int n_in,
                              void* d_out, int out_size) {
    const float* x      = (const float*)d_in[0];
    const float* sq_w   = (const float*)d_in[1];
    const float* sq_b   = (const float*)d_in[2];
    const float* aw_v   = (const float*)d_in[3];
    const float* ab_v   = (const float*)d_in[4];
    const float* w_v    = (const float*)d_in[5];
    const float* bn_v_g = (const float*)d_in[6];
    const float* bn_v_b = (const float*)d_in[7];
    const float* aw_h   = (const float*)d_in[8];
    const float* ab_h   = (const float*)d_in[9];
    const float* w_h    = (const float*)d_in[10];
    const float* bn_h_g = (const float*)d_in[11];
    const float* bn_h_b = (const float*)d_in[12];
    float* out = (float*)d_out;

    cudaFuncSetAttribute(sq_kernel, cudaFuncAttributeMaxDynamicSharedMemorySize, SQ_SMEM_BYTES);
    cudaFuncSetAttribute(v_kernel,  cudaFuncAttributeMaxDynamicSharedMemorySize, V_SMEM_BYTES);
    cudaFuncSetAttribute(h_kernel,  cudaFuncAttributeMaxDynamicSharedMemorySize, H_SMEM_BYTES);

    deint_kernel<<<N_B * C_IN, 256>>>(x);
    att_kernel<<<1, 128>>>(aw_v, ab_v, aw_h, ab_h);
    prep_kernel<<<336, 256>>>(sq_w, w_v, w_h);
    sq_kernel<<<dim3(WO/64, HO/4, N_B), 256, SQ_SMEM_BYTES>>>(x, sq_b, out);
    v_kernel<<<dim3(WO/32, HO/4, N_B), 256, V_SMEM_BYTES>>>(x);
    h_kernel<<<dim3(WO/32, HO/4, N_B), 256, H_SMEM_BYTES>>>(x);
    stats_kernel<<<256, 256>>>();
    bn_kernel<<<512, 256>>>(bn_v_g, bn_v_b, bn_h_g, bn_h_b, out);
}